// round 11
// baseline (speedup 1.0000x reference)
#include <cuda_runtime.h>

// CRF forward (log partition) on GB300 — round 8.
// One 32-thread CTA per batch; lane l owns tag l's state/bookkeeping.
// Per-step matvec acc_i = sum_j E[i][j] * p_j is SPLIT-K across the warp:
//   lane l (q=l&7, c=l>>3) reads only p[8c..8c+8) (2x LDS.128, 4x less
//   crossbar traffic than the all-read scheme) and computes 4 chunk-partials,
//   slot k holding tag tau = q + 8*(c XOR k). The XOR mapping makes the
//   cross-lane reduction a SEL-free 2-round shfl butterfly whose result for
//   tag l lands exactly on lane l.
// Log-domain kept in base-2 with a lag-2 uniform shift so the critical path
// has no ex2/lg2/shfl bookkeeping on it.

#define T_TAGS 32
#define START_TAG 30
#define STOP_TAG 31
#define LOG2E 1.4426950408889634f
#define LN2   0.6931471805599453f
#define PF 8   // emission prefetch depth (register pipeline)

__device__ __forceinline__ float ex2a(float x) {
    float r; asm("ex2.approx.f32 %0, %1;" : "=f"(r) : "f"(x)); return r;
}
__device__ __forceinline__ float lg2a(float x) {
    float r; asm("lg2.approx.f32 %0, %1;" : "=f"(r) : "f"(x)); return r;
}
__device__ __forceinline__ unsigned long long pk2(float lo, float hi) {
    unsigned long long r;
    asm("mov.b64 %0, {%1, %2};" : "=l"(r) : "f"(lo), "f"(hi));
    return r;
}
__device__ __forceinline__ void upk2(unsigned long long v, float& lo, float& hi) {
    asm("mov.b64 {%0, %1}, %2;" : "=f"(lo), "=f"(hi) : "l"(v));
}
__device__ __forceinline__ unsigned long long fma2(unsigned long long a,
                                                   unsigned long long b,
                                                   unsigned long long c) {
    unsigned long long d;
    asm("fma.rn.f32x2 %0, %1, %2, %3;" : "=l"(d) : "l"(a), "l"(b), "l"(c));
    return d;
}
__device__ __forceinline__ unsigned long long add2(unsigned long long a,
                                                   unsigned long long b) {
    unsigned long long d;
    asm("add.rn.f32x2 %0, %1, %2;" : "=l"(d) : "l"(a), "l"(b));
    return d;
}

template <int SC>
__global__ __launch_bounds__(32, 16)
void crf_fwd_kernel(const float* __restrict__ feats,
                    const float* __restrict__ trans,
                    float* __restrict__ out,
                    int S_rt) {
    const int S = (SC > 0) ? SC : S_rt;
    const int lane = threadIdx.x;
    const int q = lane & 7;
    const int c = lane >> 3;
    const int b = blockIdx.x;

    __shared__ __align__(16) float sp[2][T_TAGS];

    // ---- E in registers: slot k on lane l covers row tau = q + 8*(c^k),
    //      columns [8c, 8c+8), packed over column pairs. ----
    unsigned long long E2[4][4];
    #pragma unroll
    for (int k = 0; k < 4; k++) {
        const int row = q + 8 * (c ^ k);
        const float4* tr = reinterpret_cast<const float4*>(trans + row * T_TAGS + 8 * c);
        float4 t0 = tr[0];
        float4 t1 = tr[1];
        E2[k][0] = pk2(ex2a(t0.x * LOG2E), ex2a(t0.y * LOG2E));
        E2[k][1] = pk2(ex2a(t0.z * LOG2E), ex2a(t0.w * LOG2E));
        E2[k][2] = pk2(ex2a(t1.x * LOG2E), ex2a(t1.y * LOG2E));
        E2[k][3] = pk2(ex2a(t1.z * LOG2E), ex2a(t1.w * LOG2E));
    }
    // STOP-row transition score for this lane (log2 units), for termination
    const float t2stop = trans[STOP_TAG * T_TAGS + lane] * LOG2E;

    // ---- Emission register pipeline (PF deep) ----
    const float* f = feats + (size_t)b * (size_t)S * T_TAGS + lane;
    float ebuf[PF];
    #pragma unroll
    for (int k = 0; k < PF; k++) ebuf[k] = f[(size_t)k * T_TAGS];

    // ---- Step t=1 (closed form): alpha0 = -1e4 except START=0, so
    //      acc1_i = E[i][START] exactly in fp32. ----
    float acc = ex2a(trans[lane * T_TAGS + START_TAG] * LOG2E);

    float el = ebuf[0] * LOG2E;
    if (PF < S) ebuf[0] = f[(size_t)PF * T_TAGS];
    float lg = lg2a(acc);
    float lael = lg + el;                              // la^1 = m_1(=0) + lael
    float bc = __shfl_sync(0xffffffffu, lael, 0);      // la^1_{lane0}
    float m_cur = bc;                                  // m_2
    float m_nxt = bc;                                  // m_3
    float sc = ex2a(el - bc);                          // sc^1 = 2^{el1 + m1 - m2}
    float m_used = 0.0f;                               // m of last completed step

    // ---- Main recurrence, t = 2..S ----
    #pragma unroll 8
    for (int t = 2; t <= S; t++) {
        // --- critical path ---
        float p = acc * sc;                 // p^t_j = 2^{la^{t-1}_j - m_t}
        sp[t & 1][lane] = p;
        __syncthreads();                    // 1-warp CTA: cheap BAR, drains STS

        const ulonglong2* qq = reinterpret_cast<const ulonglong2*>(&sp[t & 1][8 * c]);
        ulonglong2 pv0 = qq[0];             // p[8c..8c+4) as 2 packed pairs
        ulonglong2 pv1 = qq[1];             // p[8c+4..8c+8)

        unsigned long long A0, A1, A2, A3;
        A0 = fma2(E2[0][0], pv0.x, 0ull);
        A1 = fma2(E2[1][0], pv0.x, 0ull);
        A2 = fma2(E2[2][0], pv0.x, 0ull);
        A3 = fma2(E2[3][0], pv0.x, 0ull);
        A0 = fma2(E2[0][1], pv0.y, A0);
        A1 = fma2(E2[1][1], pv0.y, A1);
        A2 = fma2(E2[2][1], pv0.y, A2);
        A3 = fma2(E2[3][1], pv0.y, A3);
        A0 = fma2(E2[0][2], pv1.x, A0);
        A1 = fma2(E2[1][2], pv1.x, A1);
        A2 = fma2(E2[2][2], pv1.x, A2);
        A3 = fma2(E2[3][2], pv1.x, A3);
        A0 = fma2(E2[0][3], pv1.y, A0);
        A1 = fma2(E2[1][3], pv1.y, A1);
        A2 = fma2(E2[2][3], pv1.y, A2);
        A3 = fma2(E2[3][3], pv1.y, A3);

        // SEL-free butterfly reduction (tau = q + 8*(c^k) mapping):
        // round 1 (xor 16): partner's slot2/slot3 are my slot0/slot1 tags
        A0 = add2(A0, __shfl_xor_sync(0xffffffffu, A2, 16));
        A1 = add2(A1, __shfl_xor_sync(0xffffffffu, A3, 16));
        // round 2 (xor 8): partner's slot1 is my slot0 tag
        A0 = add2(A0, __shfl_xor_sync(0xffffffffu, A1, 8));

        float lo, hi;
        upk2(A0, lo, hi);
        acc = lo + hi;                      // acc^t for tag == lane

        // --- off-critical-path bookkeeping for t+1 / t+2 ---
        lg = lg2a(acc);
        float em = ebuf[(t - 1) & (PF - 1)];
        if (t - 1 + PF < S) ebuf[(t - 1) & (PF - 1)] = f[(size_t)(t - 1 + PF) * T_TAGS];
        el = em * LOG2E;
        lael = lg + el;                                 // la^t = m_t + lael
        bc = __shfl_sync(0xffffffffu, lael, 0);
        float m_t2 = m_cur + bc;                        // m_{t+2} = la^t_0
        sc = ex2a(el + (m_cur - m_nxt));                // sc^t for p^{t+1}
        m_used = m_cur;
        m_cur = m_nxt;
        m_nxt = m_t2;
    }

    // ---- Termination: logZ = ln2 * log2sum2_j( la_j + T2[STOP][j] ) ----
    float v = m_used + lael + t2stop;  // log2 units; START lane = -inf (contributes 0)
    float vm = v;
    #pragma unroll
    for (int off = 16; off; off >>= 1)
        vm = fmaxf(vm, __shfl_xor_sync(0xffffffffu, vm, off));
    float ex = ex2a(v - vm);           // ex2a(-inf) = 0
    #pragma unroll
    for (int off = 16; off; off >>= 1)
        ex += __shfl_xor_sync(0xffffffffu, ex, off);
    if (lane == 0) out[b] = (vm + lg2a(ex)) * LN2;
}

extern "C" void kernel_launch(void* const* d_in, const int* in_sizes, int n_in,
                              void* d_out, int out_size) {
    const float* feats = (const float*)d_in[0];   // [B, S, 32]
    const float* trans = (const float*)d_in[1];   // [32, 32]
    float* out = (float*)d_out;                   // [B]

    const int B = out_size;
    const int S = in_sizes[0] / (B * T_TAGS);

    if (S == 512) {
        crf_fwd_kernel<512><<<B, 32>>>(feats, trans, out, S);
    } else {
        crf_fwd_kernel<0><<<B, 32>>>(feats, trans, out, S);
    }
}

// round 12
// speedup vs baseline: 1.1063x; 1.1063x over previous
#include <cuda_runtime.h>

// CRF forward (log partition) on GB300 — round 11.
// One 32-thread CTA per batch; lane l = tag l.
// Linear-domain recurrence with exact power-of-two rescaling every 4 steps:
//   acc_i = sum_j E[i][j] * p_j        (split-K2 matvec, 16x fma.rn.f32x2)
//   p_i   = acc_i * d_i,  d_i = exp(emit_t_i)   (one MUFU per step)
//   every 4 steps: k = exponent(acc_lane0); ishift += k (exact int);
//                  p scaled by bit-built 2^-k (exact).
// fp32 headroom: worst-case growth ~2^19/step, spread ~2^12 -> 4 steps fit
// comfortably under 2^127. No lg2/shfl bookkeeping on the per-step path.
//
// Split-K2 mapping: lane l (h=l>>4, r=l&15) reads p[16h..16h+16) (4x LDS.128,
// 2 distinct 16B lines each -> broadcast-cheap). Slot k covers row
// tau = r + 16*(h^k), so acc for tag l = s0 + shfl_xor16(partner s1):
// ONE scalar 32-bit shuffle on the reduce path.

#define T_TAGS 32
#define START_TAG 30
#define STOP_TAG 31
#define LOG2E 1.4426950408889634f
#define LN2   0.6931471805599453f
#define PF 8   // emission prefetch depth

__device__ __forceinline__ float ex2a(float x) {
    float r; asm("ex2.approx.f32 %0, %1;" : "=f"(r) : "f"(x)); return r;
}
__device__ __forceinline__ float lg2a(float x) {
    float r; asm("lg2.approx.f32 %0, %1;" : "=f"(r) : "f"(x)); return r;
}
__device__ __forceinline__ unsigned long long pk2(float lo, float hi) {
    unsigned long long r;
    asm("mov.b64 %0, {%1, %2};" : "=l"(r) : "f"(lo), "f"(hi));
    return r;
}
__device__ __forceinline__ void upk2(unsigned long long v, float& lo, float& hi) {
    asm("mov.b64 {%0, %1}, %2;" : "=f"(lo), "=f"(hi) : "l"(v));
}
__device__ __forceinline__ unsigned long long fma2(unsigned long long a,
                                                   unsigned long long b,
                                                   unsigned long long c) {
    unsigned long long d;
    asm("fma.rn.f32x2 %0, %1, %2, %3;" : "=l"(d) : "l"(a), "l"(b), "l"(c));
    return d;
}
__device__ __forceinline__ unsigned long long add2(unsigned long long a,
                                                   unsigned long long b) {
    unsigned long long d;
    asm("add.rn.f32x2 %0, %1, %2;" : "=l"(d) : "l"(a), "l"(b));
    return d;
}

template <int SC>
__global__ __launch_bounds__(32, 16)
void crf_fwd_kernel(const float* __restrict__ feats,
                    const float* __restrict__ trans,
                    float* __restrict__ out,
                    int S_rt) {
    const int S = (SC > 0) ? SC : S_rt;
    const int lane = threadIdx.x;
    const int h = lane >> 4;     // K-half owned by this lane
    const int r = lane & 15;
    const int b = blockIdx.x;

    __shared__ __align__(16) float sp[2][T_TAGS];

    // ---- E in registers: slot k holds row tau = r + 16*(h^k),
    //      columns [16h, 16h+16) packed over column pairs (8 f32x2 per slot).
    unsigned long long E2[2][8];
    #pragma unroll
    for (int k = 0; k < 2; k++) {
        const int row = r + 16 * (h ^ k);
        const float* tr = trans + row * T_TAGS + 16 * h;
        #pragma unroll
        for (int m = 0; m < 8; m++) {
            E2[k][m] = pk2(ex2a(tr[2 * m] * LOG2E),
                           ex2a(tr[2 * m + 1] * LOG2E));
        }
    }
    // STOP-row factor for termination (exp underflows to 0 for -1e4: correct).
    const float estop = ex2a(trans[STOP_TAG * T_TAGS + lane] * LOG2E);

    // ---- Emission register pipeline ----
    const float* f = feats + (size_t)b * (size_t)S * T_TAGS + lane;
    float ebuf[PF];
    #pragma unroll
    for (int k = 0; k < PF; k++) ebuf[k] = f[(size_t)k * T_TAGS];

    // ---- State: p = exp(alpha - ln2*ishift), init one-hot at START ----
    float p = (lane == START_TAG) ? 1.0f : 0.0f;
    int ishift = 0;

    #pragma unroll 8
    for (int t = 0; t < S; t++) {
        // d = exp(emit_t) — MUFU latency hidden under the matvec chain
        float d = ex2a(ebuf[t & (PF - 1)] * LOG2E);
        if (t + PF < S) ebuf[t & (PF - 1)] = f[(size_t)(t + PF) * T_TAGS];

        // --- exchange p ---
        sp[t & 1][lane] = p;
        __syncthreads();   // 1-warp CTA: cheap BAR, drains STS

        const ulonglong2* q =
            reinterpret_cast<const ulonglong2*>(&sp[t & 1][16 * h]);
        ulonglong2 v0 = q[0];   // p[16h+0 .. +4)
        ulonglong2 v1 = q[1];   // p[16h+4 .. +8)
        ulonglong2 v2 = q[2];   // p[16h+8 .. +12)
        ulonglong2 v3 = q[3];   // p[16h+12.. +16)

        // --- 16x fma2, 4 independent chains of depth 4 ---
        unsigned long long A0a, A0b, A1a, A1b;
        A0a = fma2(E2[0][0], v0.x, 0ull);
        A1a = fma2(E2[1][0], v0.x, 0ull);
        A0b = fma2(E2[0][1], v0.y, 0ull);
        A1b = fma2(E2[1][1], v0.y, 0ull);
        A0a = fma2(E2[0][2], v1.x, A0a);
        A1a = fma2(E2[1][2], v1.x, A1a);
        A0b = fma2(E2[0][3], v1.y, A0b);
        A1b = fma2(E2[1][3], v1.y, A1b);
        A0a = fma2(E2[0][4], v2.x, A0a);
        A1a = fma2(E2[1][4], v2.x, A1a);
        A0b = fma2(E2[0][5], v2.y, A0b);
        A1b = fma2(E2[1][5], v2.y, A1b);
        A0a = fma2(E2[0][6], v3.x, A0a);
        A1a = fma2(E2[1][6], v3.x, A1a);
        A0b = fma2(E2[0][7], v3.y, A0b);
        A1b = fma2(E2[1][7], v3.y, A1b);

        unsigned long long A0 = add2(A0a, A0b);
        unsigned long long A1 = add2(A1a, A1b);
        float a0lo, a0hi, a1lo, a1hi;
        upk2(A0, a0lo, a0hi);
        upk2(A1, a1lo, a1hi);
        float s0 = a0lo + a0hi;                 // my half, tag = lane
        float s1 = a1lo + a1hi;                 // my half, tag = lane^16
        // partner (lane^16) computed the other half of MY tag in its s1:
        float acc = s0 + __shfl_xor_sync(0xffffffffu, s1, 16);

        // --- apply emission; exact pow2 rescale every 4 steps ---
        if ((t & 3) == 3) {
            float bc = __shfl_sync(0xffffffffu, acc, 0);
            int k = ((__float_as_int(bc) >> 23) & 0xff) - 127;
            ishift += k;                                    // exact
            float rs = __int_as_float((127 - k) << 23);     // 2^-k, exact
            p = acc * (d * rs);
        } else {
            p = acc * d;
        }
    }

    // ---- Termination: logZ = ln2 * (ishift + log2( sum_j p_j * estop_j )) ----
    float v = p * estop;
    #pragma unroll
    for (int off = 16; off; off >>= 1)
        v += __shfl_xor_sync(0xffffffffu, v, off);
    if (lane == 0) out[b] = ((float)ishift + lg2a(v)) * LN2;
}

extern "C" void kernel_launch(void* const* d_in, const int* in_sizes, int n_in,
                              void* d_out, int out_size) {
    const float* feats = (const float*)d_in[0];   // [B, S, 32]
    const float* trans = (const float*)d_in[1];   // [32, 32]
    float* out = (float*)d_out;                   // [B]

    const int B = out_size;
    const int S = in_sizes[0] / (B * T_TAGS);

    if (S == 512) {
        crf_fwd_kernel<512><<<B, 32>>>(feats, trans, out, S);
    } else {
        crf_fwd_kernel<0><<<B, 32>>>(feats, trans, out, S);
    }
}

// round 13
// speedup vs baseline: 1.1070x; 1.0007x over previous
#include <cuda_runtime.h>

// CRF forward (log partition) on GB300 — round 11.
// One 32-thread CTA per batch; lane l = tag l.
// Linear-domain recurrence with exact power-of-two rescaling every 4 steps:
//   acc_i = sum_j E[i][j] * p_j        (split-K2 matvec, 16x fma.rn.f32x2)
//   p_i   = acc_i * d_i,  d_i = exp(emit_t_i)   (one MUFU per step)
//   every 4 steps: k = exponent(acc_lane0); ishift += k (exact int);
//                  p scaled by bit-built 2^-k (exact).
// fp32 headroom: worst-case growth ~2^19/step, spread ~2^12 -> 4 steps fit
// comfortably under 2^127. No lg2/shfl bookkeeping on the per-step path.
//
// Split-K2 mapping: lane l (h=l>>4, r=l&15) reads p[16h..16h+16) (4x LDS.128,
// 2 distinct 16B lines each -> broadcast-cheap). Slot k covers row
// tau = r + 16*(h^k), so acc for tag l = s0 + shfl_xor16(partner s1):
// ONE scalar 32-bit shuffle on the reduce path.

#define T_TAGS 32
#define START_TAG 30
#define STOP_TAG 31
#define LOG2E 1.4426950408889634f
#define LN2   0.6931471805599453f
#define PF 8   // emission prefetch depth

__device__ __forceinline__ float ex2a(float x) {
    float r; asm("ex2.approx.f32 %0, %1;" : "=f"(r) : "f"(x)); return r;
}
__device__ __forceinline__ float lg2a(float x) {
    float r; asm("lg2.approx.f32 %0, %1;" : "=f"(r) : "f"(x)); return r;
}
__device__ __forceinline__ unsigned long long pk2(float lo, float hi) {
    unsigned long long r;
    asm("mov.b64 %0, {%1, %2};" : "=l"(r) : "f"(lo), "f"(hi));
    return r;
}
__device__ __forceinline__ void upk2(unsigned long long v, float& lo, float& hi) {
    asm("mov.b64 {%0, %1}, %2;" : "=f"(lo), "=f"(hi) : "l"(v));
}
__device__ __forceinline__ unsigned long long fma2(unsigned long long a,
                                                   unsigned long long b,
                                                   unsigned long long c) {
    unsigned long long d;
    asm("fma.rn.f32x2 %0, %1, %2, %3;" : "=l"(d) : "l"(a), "l"(b), "l"(c));
    return d;
}
__device__ __forceinline__ unsigned long long add2(unsigned long long a,
                                                   unsigned long long b) {
    unsigned long long d;
    asm("add.rn.f32x2 %0, %1, %2;" : "=l"(d) : "l"(a), "l"(b));
    return d;
}

template <int SC>
__global__ __launch_bounds__(32, 16)
void crf_fwd_kernel(const float* __restrict__ feats,
                    const float* __restrict__ trans,
                    float* __restrict__ out,
                    int S_rt) {
    const int S = (SC > 0) ? SC : S_rt;
    const int lane = threadIdx.x;
    const int h = lane >> 4;     // K-half owned by this lane
    const int r = lane & 15;
    const int b = blockIdx.x;

    __shared__ __align__(16) float sp[2][T_TAGS];

    // ---- E in registers: slot k holds row tau = r + 16*(h^k),
    //      columns [16h, 16h+16) packed over column pairs (8 f32x2 per slot).
    unsigned long long E2[2][8];
    #pragma unroll
    for (int k = 0; k < 2; k++) {
        const int row = r + 16 * (h ^ k);
        const float* tr = trans + row * T_TAGS + 16 * h;
        #pragma unroll
        for (int m = 0; m < 8; m++) {
            E2[k][m] = pk2(ex2a(tr[2 * m] * LOG2E),
                           ex2a(tr[2 * m + 1] * LOG2E));
        }
    }
    // STOP-row factor for termination (exp underflows to 0 for -1e4: correct).
    const float estop = ex2a(trans[STOP_TAG * T_TAGS + lane] * LOG2E);

    // ---- Emission register pipeline ----
    const float* f = feats + (size_t)b * (size_t)S * T_TAGS + lane;
    float ebuf[PF];
    #pragma unroll
    for (int k = 0; k < PF; k++) ebuf[k] = f[(size_t)k * T_TAGS];

    // ---- State: p = exp(alpha - ln2*ishift), init one-hot at START ----
    float p = (lane == START_TAG) ? 1.0f : 0.0f;
    int ishift = 0;

    #pragma unroll 8
    for (int t = 0; t < S; t++) {
        // d = exp(emit_t) — MUFU latency hidden under the matvec chain
        float d = ex2a(ebuf[t & (PF - 1)] * LOG2E);
        if (t + PF < S) ebuf[t & (PF - 1)] = f[(size_t)(t + PF) * T_TAGS];

        // --- exchange p ---
        sp[t & 1][lane] = p;
        __syncthreads();   // 1-warp CTA: cheap BAR, drains STS

        const ulonglong2* q =
            reinterpret_cast<const ulonglong2*>(&sp[t & 1][16 * h]);
        ulonglong2 v0 = q[0];   // p[16h+0 .. +4)
        ulonglong2 v1 = q[1];   // p[16h+4 .. +8)
        ulonglong2 v2 = q[2];   // p[16h+8 .. +12)
        ulonglong2 v3 = q[3];   // p[16h+12.. +16)

        // --- 16x fma2, 4 independent chains of depth 4 ---
        unsigned long long A0a, A0b, A1a, A1b;
        A0a = fma2(E2[0][0], v0.x, 0ull);
        A1a = fma2(E2[1][0], v0.x, 0ull);
        A0b = fma2(E2[0][1], v0.y, 0ull);
        A1b = fma2(E2[1][1], v0.y, 0ull);
        A0a = fma2(E2[0][2], v1.x, A0a);
        A1a = fma2(E2[1][2], v1.x, A1a);
        A0b = fma2(E2[0][3], v1.y, A0b);
        A1b = fma2(E2[1][3], v1.y, A1b);
        A0a = fma2(E2[0][4], v2.x, A0a);
        A1a = fma2(E2[1][4], v2.x, A1a);
        A0b = fma2(E2[0][5], v2.y, A0b);
        A1b = fma2(E2[1][5], v2.y, A1b);
        A0a = fma2(E2[0][6], v3.x, A0a);
        A1a = fma2(E2[1][6], v3.x, A1a);
        A0b = fma2(E2[0][7], v3.y, A0b);
        A1b = fma2(E2[1][7], v3.y, A1b);

        unsigned long long A0 = add2(A0a, A0b);
        unsigned long long A1 = add2(A1a, A1b);
        float a0lo, a0hi, a1lo, a1hi;
        upk2(A0, a0lo, a0hi);
        upk2(A1, a1lo, a1hi);
        float s0 = a0lo + a0hi;                 // my half, tag = lane
        float s1 = a1lo + a1hi;                 // my half, tag = lane^16
        // partner (lane^16) computed the other half of MY tag in its s1:
        float acc = s0 + __shfl_xor_sync(0xffffffffu, s1, 16);

        // --- apply emission; exact pow2 rescale every 4 steps ---
        if ((t & 3) == 3) {
            float bc = __shfl_sync(0xffffffffu, acc, 0);
            int k = ((__float_as_int(bc) >> 23) & 0xff) - 127;
            ishift += k;                                    // exact
            float rs = __int_as_float((127 - k) << 23);     // 2^-k, exact
            p = acc * (d * rs);
        } else {
            p = acc * d;
        }
    }

    // ---- Termination: logZ = ln2 * (ishift + log2( sum_j p_j * estop_j )) ----
    float v = p * estop;
    #pragma unroll
    for (int off = 16; off; off >>= 1)
        v += __shfl_xor_sync(0xffffffffu, v, off);
    if (lane == 0) out[b] = ((float)ishift + lg2a(v)) * LN2;
}

extern "C" void kernel_launch(void* const* d_in, const int* in_sizes, int n_in,
                              void* d_out, int out_size) {
    const float* feats = (const float*)d_in[0];   // [B, S, 32]
    const float* trans = (const float*)d_in[1];   // [32, 32]
    float* out = (float*)d_out;                   // [B]

    const int B = out_size;
    const int S = in_sizes[0] / (B * T_TAGS);

    if (S == 512) {
        crf_fwd_kernel<512><<<B, 32>>>(feats, trans, out, S);
    } else {
        crf_fwd_kernel<0><<<B, 32>>>(feats, trans, out, S);
    }
}